// round 15
// baseline (speedup 1.0000x reference)
#include <cuda_runtime.h>
#include <cuda_bf16.h>
#include <cuda_fp16.h>
#include <cstdint>

#define H 128
#define NMAX 100000
#define TM 128
#define MLP_THREADS 512
#define ROWSTRIDE 72                        // u32 per row: 8-bank row skew -> conflict-free LDS.64
#define TILE_U32 (128 * ROWSTRIDE)          // 9216 u32 per hi/lo buffer
#define MLP_SMEM (6 * TILE_U32 * 4)         // Hs(hi,lo) + Ts0(hi,lo) + Ts1(hi,lo) = 221184 B
#define WPREP_TOTAL (3 * 8 * 4 * 2 * 8 * 32 * 2)

// Scratch (device globals: no allocation allowed)
__device__ __align__(16) float g_x[(size_t)NMAX * H];
__device__ __align__(16) float g_h[(size_t)NMAX * H];
__device__ __align__(16) uint32_t g_xh[(size_t)NMAX * 64];  // fp16 mirror of x
// weight fragments: [layer][warpslot 8][img 4][nb 2][ks 8][lane 32][2] u32
__device__ __align__(16) uint32_t g_wfrag[WPREP_TOTAL];

__device__ __forceinline__ uint32_t pack_bf16(float x, float y) {
    __nv_bfloat162 t = __floats2bfloat162_rn(x, y);
    return *(uint32_t*)&t;
}
__device__ __forceinline__ uint32_t pack_f16(float x, float y) {
    __half2 t = __floats2half2_rn(x, y);
    return *(uint32_t*)&t;
}
// permuted pair index: pair j (cols 2j,2j+1) -> slot so that a0/a2 are adjacent
__device__ __forceinline__ int pidx(int j) {
    return ((j >> 3) << 3) + ((j & 3) << 1) + ((j >> 2) & 1);
}
__device__ __forceinline__ float silu_fast(float f) {
    float th;
    asm("tanh.approx.f32 %0, %1;" : "=f"(th) : "f"(0.5f * f));
    return f * fmaf(0.5f, th, 0.5f);
}

#define MMA_BF16(c, A0, A1, A2, A3, B0, B1)                                   \
    asm volatile("mma.sync.aligned.m16n8k16.row.col.f32.bf16.bf16.f32 "       \
                 "{%0,%1,%2,%3}, {%4,%5,%6,%7}, {%8,%9}, {%0,%1,%2,%3};"      \
                 : "+f"(c[0]), "+f"(c[1]), "+f"(c[2]), "+f"(c[3])             \
                 : "r"(A0), "r"(A1), "r"(A2), "r"(A3), "r"(B0), "r"(B1));

// ---------------------------------------------------------------------------
// Fused prep: blocks [0, nembed): embedding gather (x, h, xh init);
// [nembed, nembed+nwprep): W1/W2 bf16 hi/lo fragment split;
// [nembed+nwprep, +nbatch): batch_vec -> float output tail.
// ---------------------------------------------------------------------------
__global__ void prep_kernel(const float* __restrict__ emb,
                            const int* __restrict__ z,
                            float* __restrict__ x, float* __restrict__ h,
                            uint32_t* __restrict__ xh,
                            int n, int nembed, int nwprep,
                            const float* __restrict__ W1,
                            const float* __restrict__ W2,
                            const int* __restrict__ bv,
                            float* __restrict__ out_tail) {
    int b = blockIdx.x;
    if (b < nembed) {
        int i = b * 256 + threadIdx.x;
        if (i >= n * 32) return;
        int node = i >> 5;
        int c = i & 31;
        float4 v = ((const float4*)emb)[(size_t)z[node] * 32 + c];
        ((float4*)x)[i] = v;
        ((float4*)h)[i] = v;
        uint2 p;
        p.x = pack_f16(v.x, v.y);
        p.y = pack_f16(v.z, v.w);
        ((uint2*)xh)[(size_t)node * 32 + c] = p;
    } else if (b < nembed + nwprep) {
        int idx = (b - nembed) * 256 + threadIdx.x;
        if (idx >= WPREP_TOTAL) return;
        int r    = idx & 1;
        int lane = (idx >> 1) & 31;
        int ks   = (idx >> 6) & 7;
        int nb   = (idx >> 9) & 1;
        int img  = (idx >> 10) & 3;
        int w    = (idx >> 12) & 7;
        int l    = idx >> 15;
        int gid = lane >> 2, tg = lane & 3;
        int mat = img >> 1, hl = img & 1;
        int nn = w * 16 + nb * 8 + gid;
        int k0 = ks * 16 + tg * 2 + r * 8;
        const float* W = (mat ? W2 : W1) + (size_t)l * H * H;
        float v0 = W[k0 * H + nn];
        float v1 = W[(k0 + 1) * H + nn];
        __nv_bfloat16 h0 = __float2bfloat16(v0);
        __nv_bfloat16 h1 = __float2bfloat16(v1);
        float o0 = hl ? (v0 - __bfloat162float(h0)) : __bfloat162float(h0);
        float o1 = hl ? (v1 - __bfloat162float(h1)) : __bfloat162float(h1);
        g_wfrag[idx] = pack_bf16(o0, o1);
    } else {
        if (!out_tail) return;
        int i = (b - nembed - nwprep) * 256 + threadIdx.x;
        if (i < n) out_tail[i] = (float)bv[i];
    }
}

// ---------------------------------------------------------------------------
// Edge/message kernel: one warp per 4 edges, int4 index loads, fp16 gather
// (halves gather traffic), fp32 red.v4 scatter. 4 CTAs/SM.
// ---------------------------------------------------------------------------
__global__ void __launch_bounds__(256, 4)
edge_kernel(const uint32_t* __restrict__ xh,
            float* __restrict__ h,
            const float* __restrict__ edge_attr,
            const int* __restrict__ ei,
            const float* __restrict__ We,
            const float* __restrict__ be,
            int E) {
    __shared__ float Wes[4 * H];
    __shared__ float bes[H];
    int tid = threadIdx.x;
    for (int i = tid; i < 4 * H; i += blockDim.x) Wes[i] = We[i];
    for (int i = tid; i < H; i += blockDim.x) bes[i] = be[i];
    __syncthreads();

    int lane = tid & 31;
    int warp = blockIdx.x * (blockDim.x >> 5) + (tid >> 5);
    int nwarps = gridDim.x * (blockDim.x >> 5);

    float4 w0 = ((const float4*)Wes)[0 * 32 + lane];
    float4 w1 = ((const float4*)Wes)[1 * 32 + lane];
    float4 w2 = ((const float4*)Wes)[2 * 32 + lane];
    float4 w3 = ((const float4*)Wes)[3 * 32 + lane];
    float4 bb = ((const float4*)bes)[lane];

    int E4 = E & ~3;
    int stride = nwarps * 4;
    #pragma unroll 1
    for (int e0 = warp * 4; e0 < E4; e0 += stride) {
        int4 sv = *(const int4*)(ei + e0);       // 4 src indices
        int4 dv = *(const int4*)(ei + E + e0);   // 4 dst indices
        int s[4] = { sv.x, sv.y, sv.z, sv.w };
        int d[4] = { dv.x, dv.y, dv.z, dv.w };
        float4 ea[4];
        uint2 xr[4];
        #pragma unroll
        for (int j = 0; j < 4; j++) ea[j] = ((const float4*)edge_attr)[e0 + j];
        #pragma unroll
        for (int j = 0; j < 4; j++)
            xr[j] = ((const uint2*)xh)[(size_t)s[j] * 32 + lane];
        #pragma unroll
        for (int j = 0; j < 4; j++) {
            float2 lo = __half22float2(*(__half2*)&xr[j].x);
            float2 hi = __half22float2(*(__half2*)&xr[j].y);
            float m0 = lo.x + bb.x + ea[j].x * w0.x + ea[j].y * w1.x + ea[j].z * w2.x + ea[j].w * w3.x;
            float m1 = lo.y + bb.y + ea[j].x * w0.y + ea[j].y * w1.y + ea[j].z * w2.y + ea[j].w * w3.y;
            float m2 = hi.x + bb.z + ea[j].x * w0.z + ea[j].y * w1.z + ea[j].z * w2.z + ea[j].w * w3.z;
            float m3 = hi.y + bb.w + ea[j].x * w0.w + ea[j].y * w1.w + ea[j].z * w2.w + ea[j].w * w3.w;
            m0 = fmaxf(m0, 0.f); m1 = fmaxf(m1, 0.f);
            m2 = fmaxf(m2, 0.f); m3 = fmaxf(m3, 0.f);
            float* dptr = h + (size_t)d[j] * H + lane * 4;
            asm volatile("red.global.add.v4.f32 [%0], {%1,%2,%3,%4};"
                         :: "l"(dptr), "f"(m0), "f"(m1), "f"(m2), "f"(m3)
                         : "memory");
        }
    }
    // tail (E not multiple of 4)
    if (warp == 0) {
        for (int e = E4 + (tid >> 5); e < E; e += 8) {
            int src = ei[e], dst = ei[E + e];
            float4 eav = ((const float4*)edge_attr)[e];
            uint2 xr = ((const uint2*)xh)[(size_t)src * 32 + lane];
            float2 lo = __half22float2(*(__half2*)&xr.x);
            float2 hi = __half22float2(*(__half2*)&xr.y);
            float m0 = lo.x + bb.x + eav.x * w0.x + eav.y * w1.x + eav.z * w2.x + eav.w * w3.x;
            float m1 = lo.y + bb.y + eav.x * w0.y + eav.y * w1.y + eav.z * w2.y + eav.w * w3.y;
            float m2 = hi.x + bb.z + eav.x * w0.z + eav.y * w1.z + eav.z * w2.z + eav.w * w3.z;
            float m3 = hi.y + bb.w + eav.x * w0.w + eav.y * w1.w + eav.z * w2.w + eav.w * w3.w;
            m0 = fmaxf(m0, 0.f); m1 = fmaxf(m1, 0.f);
            m2 = fmaxf(m2, 0.f); m3 = fmaxf(m3, 0.f);
            float* dptr = h + (size_t)dst * H + lane * 4;
            asm volatile("red.global.add.v4.f32 [%0], {%1,%2,%3,%4};"
                         :: "l"(dptr), "f"(m0), "f"(m1), "f"(m2), "f"(m3)
                         : "memory");
        }
    }
}

// ---------------------------------------------------------------------------
// Warp-specialized fused 2-layer MLP (bf16x3 mma.sync):
//   convert(t): split across BOTH groups at iteration top (rows 0-63 / 64-127)
//   warps 0-7  (group 0): GEMM1(t) -> silu -> Ts[buf]
//   warps 8-15 (group 1): GEMM2(t-1) from Ts[buf^1] -> bias -> gmem (+fp16 mirror)
// ---------------------------------------------------------------------------
__global__ void __launch_bounds__(MLP_THREADS, 1)
mlp_kernel(const float* __restrict__ h_in,
           const uint32_t* __restrict__ wfrag,
           const float* __restrict__ b1, const float* __restrict__ b2,
           float* __restrict__ x_out, float* __restrict__ h_out,
           uint32_t* __restrict__ xh_out, int n) {
    extern __shared__ __align__(16) uint32_t sm[];
    uint32_t* Hs_hi = sm;
    uint32_t* Hs_lo = sm + TILE_U32;
    // Ts buffers: sm + (2 + 2*buf)*TILE_U32 (hi), +TILE_U32 (lo)

    int tid = threadIdx.x, w = tid >> 5, lane = tid & 31;
    int group = w >> 3;          // 0 = W1 group, 1 = W2/store group
    int wl = w & 7;              // warp slot within group (16-col slice)
    int gt = tid & 255;          // thread index within group
    int gid = lane >> 2, tg = lane & 3;

    // this warp's weight fragments for ITS matrix only (64 regs)
    uint2 wB[2][2][8];           // [hl][nb][ks]
    {
        const uint2* wp = (const uint2*)wfrag + (size_t)wl * 4 * 2 * 8 * 32;
        #pragma unroll
        for (int hl = 0; hl < 2; hl++)
            #pragma unroll
            for (int nb = 0; nb < 2; nb++)
                #pragma unroll
                for (int ks = 0; ks < 8; ks++)
                    wB[hl][nb][ks] =
                        wp[((((group * 2 + hl) * 2) + nb) * 8 + ks) * 32 + lane];
    }
    const float* bsrc = group ? b2 : b1;
    float2 bv[2];
    #pragma unroll
    for (int nb = 0; nb < 2; nb++)
        bv[nb] = *(const float2*)(bsrc + 16 * wl + 8 * nb + 2 * tg);

    int ntiles = (n + TM - 1) / TM;
    int bid = blockIdx.x;
    int ntl = (bid < ntiles) ? ((ntiles - 1 - bid) / gridDim.x + 1) : 0;

    #pragma unroll 1
    for (int it = 0; it <= ntl; it++) {
        int buf = it & 1;

        // ---- convert tile t=it (both groups, half each) ----
        if (it < ntl) {
            int row0 = (bid + it * gridDim.x) * TM;
            #pragma unroll 4
            for (int it2 = 0; it2 < 8; it2++) {
                int i = gt + (group * 8 + it2) * 256;
                int row = i >> 5;
                int c4 = i & 31;
                float4 v = make_float4(0.f, 0.f, 0.f, 0.f);
                if (row0 + row < n)
                    v = *(const float4*)(h_in + (size_t)(row0 + row) * H + c4 * 4);
                __nv_bfloat16 hx = __float2bfloat16(v.x), hy = __float2bfloat16(v.y);
                __nv_bfloat16 hz = __float2bfloat16(v.z), hw = __float2bfloat16(v.w);
                int base = row * ROWSTRIDE;
                int p0 = pidx(2 * c4), p1 = pidx(2 * c4 + 1);
                Hs_hi[base + p0] = pack_bf16(__bfloat162float(hx), __bfloat162float(hy));
                Hs_hi[base + p1] = pack_bf16(__bfloat162float(hz), __bfloat162float(hw));
                Hs_lo[base + p0] = pack_bf16(v.x - __bfloat162float(hx), v.y - __bfloat162float(hy));
                Hs_lo[base + p1] = pack_bf16(v.z - __bfloat162float(hz), v.w - __bfloat162float(hw));
            }
        }
        __syncthreads();

        if (group == 0) {
            if (it < ntl) {
                // ---- GEMM1 + silu -> Ts[buf] ----
                uint32_t* Ts_hi = sm + (2 + 2 * buf) * TILE_U32;
                uint32_t* Ts_lo = Ts_hi + TILE_U32;
                #pragma unroll 1
                for (int mb = 0; mb < 8; mb++) {
                    float acc[2][4] = {{0.f, 0.f, 0.f, 0.f}, {0.f, 0.f, 0.f, 0.f}};
                    int ra = (mb * 16 + gid) * ROWSTRIDE;
                    int rb = ra + 8 * ROWSTRIDE;
                    #pragma unroll
                    for (int ks = 0; ks < 8; ks++) {
                        uint2 ah  = *(const uint2*)(Hs_hi + ra + ks * 8 + tg * 2);
                        uint2 ahb = *(const uint2*)(Hs_hi + rb + ks * 8 + tg * 2);
                        uint2 al  = *(const uint2*)(Hs_lo + ra + ks * 8 + tg * 2);
                        uint2 alb = *(const uint2*)(Hs_lo + rb + ks * 8 + tg * 2);
                        #pragma unroll
                        for (int nb = 0; nb < 2; nb++) {
                            uint2 bh = wB[0][nb][ks];
                            uint2 bl = wB[1][nb][ks];
                            MMA_BF16(acc[nb], ah.x, ahb.x, ah.y, ahb.y, bh.x, bh.y);
                            MMA_BF16(acc[nb], al.x, alb.x, al.y, alb.y, bh.x, bh.y);
                            MMA_BF16(acc[nb], ah.x, ahb.x, ah.y, ahb.y, bl.x, bl.y);
                        }
                    }
                    int sa = (mb * 16 + gid) * ROWSTRIDE + 8 * wl + 2 * tg;
                    int sb = sa + 8 * ROWSTRIDE;
                    #pragma unroll
                    for (int nb = 0; nb < 2; nb++) {
                        float f0 = silu_fast(acc[nb][0] + bv[nb].x);
                        float f1 = silu_fast(acc[nb][1] + bv[nb].y);
                        float f2 = silu_fast(acc[nb][2] + bv[nb].x);
                        float f3 = silu_fast(acc[nb][3] + bv[nb].y);
                        __nv_bfloat16 h0 = __float2bfloat16(f0), h1 = __float2bfloat16(f1);
                        __nv_bfloat16 h2 = __float2bfloat16(f2), h3 = __float2bfloat16(f3);
                        Ts_hi[sa + nb] = pack_bf16(__bfloat162float(h0), __bfloat162float(h1));
                        Ts_hi[sb + nb] = pack_bf16(__bfloat162float(h2), __bfloat162float(h3));
                        Ts_lo[sa + nb] = pack_bf16(f0 - __bfloat162float(h0), f1 - __bfloat162float(h1));
                        Ts_lo[sb + nb] = pack_bf16(f2 - __bfloat162float(h2), f3 - __bfloat162float(h3));
                    }
                }
            }
        } else {
            if (it > 0) {
                int row0 = (bid + (it - 1) * gridDim.x) * TM;
                uint32_t* Ts_hi = sm + (2 + 2 * (buf ^ 1)) * TILE_U32;
                uint32_t* Ts_lo = Ts_hi + TILE_U32;
                #pragma unroll 1
                for (int mb = 0; mb < 8; mb++) {
                    float acc[2][4] = {{0.f, 0.f, 0.f, 0.f}, {0.f, 0.f, 0.f, 0.f}};
                    int ra = (mb * 16 + gid) * ROWSTRIDE;
                    int rb = ra + 8 * ROWSTRIDE;
                    #pragma unroll
                    for (int ks = 0; ks < 8; ks++) {
                        uint2 ah  = *(const uint2*)(Ts_hi + ra + ks * 8 + tg * 2);
                        uint2 ahb = *(const uint2*)(Ts_hi + rb + ks * 8 + tg * 2);
                        uint2 al  = *(const uint2*)(Ts_lo + ra + ks * 8 + tg * 2);
                        uint2 alb = *(const uint2*)(Ts_lo + rb + ks * 8 + tg * 2);
                        #pragma unroll
                        for (int nb = 0; nb < 2; nb++) {
                            uint2 bh = wB[0][nb][ks];
                            uint2 bl = wB[1][nb][ks];
                            MMA_BF16(acc[nb], ah.x, ahb.x, ah.y, ahb.y, bh.x, bh.y);
                            MMA_BF16(acc[nb], al.x, alb.x, al.y, alb.y, bh.x, bh.y);
                            MMA_BF16(acc[nb], ah.x, ahb.x, ah.y, ahb.y, bl.x, bl.y);
                        }
                    }
                    int r0 = row0 + mb * 16 + gid;
                    int r1 = r0 + 8;
                    #pragma unroll
                    for (int nb = 0; nb < 2; nb++) {
                        int col = 16 * wl + 8 * nb + 2 * tg;
                        if (r0 < n) {
                            float2 o0 = make_float2(acc[nb][0] + bv[nb].x,
                                                    acc[nb][1] + bv[nb].y);
                            *(float2*)(x_out + (size_t)r0 * H + col) = o0;
                            if (h_out) {
                                *(float2*)(h_out + (size_t)r0 * H + col) = o0;
                                xh_out[(size_t)r0 * 64 + (col >> 1)] = pack_f16(o0.x, o0.y);
                            }
                        }
                        if (r1 < n) {
                            float2 o1 = make_float2(acc[nb][2] + bv[nb].x,
                                                    acc[nb][3] + bv[nb].y);
                            *(float2*)(x_out + (size_t)r1 * H + col) = o1;
                            if (h_out) {
                                *(float2*)(h_out + (size_t)r1 * H + col) = o1;
                                xh_out[(size_t)r1 * 64 + (col >> 1)] = pack_f16(o1.x, o1.y);
                            }
                        }
                    }
                }
            }
        }
        __syncthreads();
    }
}

extern "C" void kernel_launch(void* const* d_in, const int* in_sizes, int n_in,
                              void* d_out, int out_size) {
    const float* emb       = (const float*)d_in[0];
    const float* We        = (const float*)d_in[1];
    const float* be        = (const float*)d_in[2];
    const float* W1        = (const float*)d_in[3];
    const float* b1        = (const float*)d_in[4];
    const float* W2        = (const float*)d_in[5];
    const float* b2        = (const float*)d_in[6];
    const float* edge_attr = (const float*)d_in[7];
    const int*   z         = (const int*)d_in[8];
    const int*   ei        = (const int*)d_in[9];
    const int*   bv        = (const int*)d_in[10];

    int n = in_sizes[8];
    int E = in_sizes[9] / 2;
    float* out = (float*)d_out;

    float *gx, *gh;
    uint32_t *gwf, *gxh;
    cudaGetSymbolAddress((void**)&gx, g_x);
    cudaGetSymbolAddress((void**)&gh, g_h);
    cudaGetSymbolAddress((void**)&gwf, g_wfrag);
    cudaGetSymbolAddress((void**)&gxh, g_xh);

    cudaFuncSetAttribute(mlp_kernel, cudaFuncAttributeMaxDynamicSharedMemorySize,
                         MLP_SMEM);

    int nembed = (n * 32 + 255) / 256;
    int nwprep = (WPREP_TOTAL + 255) / 256;
    int nbatch = (n + 255) / 256;
    float* out_tail = (out_size >= n * H + n) ? (out + (size_t)n * H) : nullptr;
    prep_kernel<<<nembed + nwprep + nbatch, 256>>>(emb, z, gx, gh, gxh, n, nembed,
                                                   nwprep, W1, W2, bv, out_tail);

    for (int l = 0; l < 3; l++) {
        edge_kernel<<<4096, 256>>>(gxh, gh, edge_attr, ei,
                                   We + (size_t)l * 4 * H, be + (size_t)l * H, E);
        bool last = (l == 2);
        mlp_kernel<<<148, MLP_THREADS, MLP_SMEM>>>(
            gh,
            gwf + (size_t)l * 8 * 4 * 2 * 8 * 32 * 2,
            b1 + (size_t)l * H, b2 + (size_t)l * H,
            last ? out : gx,
            last ? nullptr : gh,
            gxh,
            n);
    }
}

// round 16
// speedup vs baseline: 1.0776x; 1.0776x over previous
#include <cuda_runtime.h>
#include <cuda_bf16.h>
#include <cuda_fp16.h>
#include <cstdint>

#define H 128
#define NMAX 100000
#define TM 128
#define MLP_THREADS 512
#define ROWSTRIDE 72                        // u32 per row: 8-bank row skew -> conflict-free LDS.64
#define TILE_U32 (128 * ROWSTRIDE)          // 9216 u32 per hi/lo buffer
#define MLP_SMEM (6 * TILE_U32 * 4)         // Hs(hi,lo) + Ts0(hi,lo) + Ts1(hi,lo) = 221184 B
#define WPREP_TOTAL (3 * 8 * 4 * 2 * 8 * 32 * 2)

// Scratch (device globals: no allocation allowed)
__device__ __align__(16) float g_h[(size_t)NMAX * H];
__device__ __align__(16) uint32_t g_xh[(size_t)NMAX * 64];  // fp16 mirror of x
// weight fragments: [layer][warpslot 8][img 4][nb 2][ks 8][lane 32][2] u32
__device__ __align__(16) uint32_t g_wfrag[WPREP_TOTAL];

__device__ __forceinline__ uint32_t pack_bf16(float x, float y) {
    __nv_bfloat162 t = __floats2bfloat162_rn(x, y);
    return *(uint32_t*)&t;
}
__device__ __forceinline__ uint32_t pack_f16(float x, float y) {
    __half2 t = __floats2half2_rn(x, y);
    return *(uint32_t*)&t;
}
// permuted pair index: pair j (cols 2j,2j+1) -> slot so that a0/a2 are adjacent
__device__ __forceinline__ int pidx(int j) {
    return ((j >> 3) << 3) + ((j & 3) << 1) + ((j >> 2) & 1);
}
__device__ __forceinline__ float silu_fast(float f) {
    float th;
    asm("tanh.approx.f32 %0, %1;" : "=f"(th) : "f"(0.5f * f));
    return f * fmaf(0.5f, th, 0.5f);
}

#define MMA_BF16(c, A0, A1, A2, A3, B0, B1)                                   \
    asm volatile("mma.sync.aligned.m16n8k16.row.col.f32.bf16.bf16.f32 "       \
                 "{%0,%1,%2,%3}, {%4,%5,%6,%7}, {%8,%9}, {%0,%1,%2,%3};"      \
                 : "+f"(c[0]), "+f"(c[1]), "+f"(c[2]), "+f"(c[3])             \
                 : "r"(A0), "r"(A1), "r"(A2), "r"(A3), "r"(B0), "r"(B1));

// ---------------------------------------------------------------------------
// Fused prep: blocks [0, nembed): embedding gather (h, xh init; x dropped —
// nothing reads fp32 x anymore);
// [nembed, nembed+nwprep): W1/W2 bf16 hi/lo fragment split;
// [nembed+nwprep, +nbatch): batch_vec -> float output tail.
// ---------------------------------------------------------------------------
__global__ void prep_kernel(const float* __restrict__ emb,
                            const int* __restrict__ z,
                            float* __restrict__ h,
                            uint32_t* __restrict__ xh,
                            int n, int nembed, int nwprep,
                            const float* __restrict__ W1,
                            const float* __restrict__ W2,
                            const int* __restrict__ bv,
                            float* __restrict__ out_tail) {
    int b = blockIdx.x;
    if (b < nembed) {
        int i = b * 256 + threadIdx.x;
        if (i >= n * 32) return;
        int node = i >> 5;
        int c = i & 31;
        float4 v = ((const float4*)emb)[(size_t)z[node] * 32 + c];
        ((float4*)h)[i] = v;
        uint2 p;
        p.x = pack_f16(v.x, v.y);
        p.y = pack_f16(v.z, v.w);
        ((uint2*)xh)[(size_t)node * 32 + c] = p;
    } else if (b < nembed + nwprep) {
        int idx = (b - nembed) * 256 + threadIdx.x;
        if (idx >= WPREP_TOTAL) return;
        int r    = idx & 1;
        int lane = (idx >> 1) & 31;
        int ks   = (idx >> 6) & 7;
        int nb   = (idx >> 9) & 1;
        int img  = (idx >> 10) & 3;
        int w    = (idx >> 12) & 7;
        int l    = idx >> 15;
        int gid = lane >> 2, tg = lane & 3;
        int mat = img >> 1, hl = img & 1;
        int nn = w * 16 + nb * 8 + gid;
        int k0 = ks * 16 + tg * 2 + r * 8;
        const float* W = (mat ? W2 : W1) + (size_t)l * H * H;
        float v0 = W[k0 * H + nn];
        float v1 = W[(k0 + 1) * H + nn];
        __nv_bfloat16 h0 = __float2bfloat16(v0);
        __nv_bfloat16 h1 = __float2bfloat16(v1);
        float o0 = hl ? (v0 - __bfloat162float(h0)) : __bfloat162float(h0);
        float o1 = hl ? (v1 - __bfloat162float(h1)) : __bfloat162float(h1);
        g_wfrag[idx] = pack_bf16(o0, o1);
    } else {
        if (!out_tail) return;
        int i = (b - nembed - nwprep) * 256 + threadIdx.x;
        if (i < n) out_tail[i] = (float)bv[i];
    }
}

// ---------------------------------------------------------------------------
// Edge/message kernel: one warp per 4 edges, int4 index loads, fp16 gather
// (halves gather traffic), fp32 red.v4 scatter. 4 CTAs/SM.
// ---------------------------------------------------------------------------
__global__ void __launch_bounds__(256, 4)
edge_kernel(const uint32_t* __restrict__ xh,
            float* __restrict__ h,
            const float* __restrict__ edge_attr,
            const int* __restrict__ ei,
            const float* __restrict__ We,
            const float* __restrict__ be,
            int E) {
    __shared__ float Wes[4 * H];
    __shared__ float bes[H];
    int tid = threadIdx.x;
    for (int i = tid; i < 4 * H; i += blockDim.x) Wes[i] = We[i];
    for (int i = tid; i < H; i += blockDim.x) bes[i] = be[i];
    __syncthreads();

    int lane = tid & 31;
    int warp = blockIdx.x * (blockDim.x >> 5) + (tid >> 5);
    int nwarps = gridDim.x * (blockDim.x >> 5);

    float4 w0 = ((const float4*)Wes)[0 * 32 + lane];
    float4 w1 = ((const float4*)Wes)[1 * 32 + lane];
    float4 w2 = ((const float4*)Wes)[2 * 32 + lane];
    float4 w3 = ((const float4*)Wes)[3 * 32 + lane];
    float4 bb = ((const float4*)bes)[lane];

    int E4 = E & ~3;
    int stride = nwarps * 4;
    #pragma unroll 1
    for (int e0 = warp * 4; e0 < E4; e0 += stride) {
        int4 sv = *(const int4*)(ei + e0);       // 4 src indices
        int4 dv = *(const int4*)(ei + E + e0);   // 4 dst indices
        int s[4] = { sv.x, sv.y, sv.z, sv.w };
        int d[4] = { dv.x, dv.y, dv.z, dv.w };
        float4 ea[4];
        uint2 xr[4];
        #pragma unroll
        for (int j = 0; j < 4; j++) ea[j] = ((const float4*)edge_attr)[e0 + j];
        #pragma unroll
        for (int j = 0; j < 4; j++)
            xr[j] = ((const uint2*)xh)[(size_t)s[j] * 32 + lane];
        #pragma unroll
        for (int j = 0; j < 4; j++) {
            float2 lo = __half22float2(*(__half2*)&xr[j].x);
            float2 hi = __half22float2(*(__half2*)&xr[j].y);
            float m0 = lo.x + bb.x + ea[j].x * w0.x + ea[j].y * w1.x + ea[j].z * w2.x + ea[j].w * w3.x;
            float m1 = lo.y + bb.y + ea[j].x * w0.y + ea[j].y * w1.y + ea[j].z * w2.y + ea[j].w * w3.y;
            float m2 = hi.x + bb.z + ea[j].x * w0.z + ea[j].y * w1.z + ea[j].z * w2.z + ea[j].w * w3.z;
            float m3 = hi.y + bb.w + ea[j].x * w0.w + ea[j].y * w1.w + ea[j].z * w2.w + ea[j].w * w3.w;
            m0 = fmaxf(m0, 0.f); m1 = fmaxf(m1, 0.f);
            m2 = fmaxf(m2, 0.f); m3 = fmaxf(m3, 0.f);
            float* dptr = h + (size_t)d[j] * H + lane * 4;
            asm volatile("red.global.add.v4.f32 [%0], {%1,%2,%3,%4};"
                         :: "l"(dptr), "f"(m0), "f"(m1), "f"(m2), "f"(m3)
                         : "memory");
        }
    }
    // tail (E not multiple of 4)
    if (warp == 0) {
        for (int e = E4 + (tid >> 5); e < E; e += 8) {
            int src = ei[e], dst = ei[E + e];
            float4 eav = ((const float4*)edge_attr)[e];
            uint2 xr = ((const uint2*)xh)[(size_t)src * 32 + lane];
            float2 lo = __half22float2(*(__half2*)&xr.x);
            float2 hi = __half22float2(*(__half2*)&xr.y);
            float m0 = lo.x + bb.x + eav.x * w0.x + eav.y * w1.x + eav.z * w2.x + eav.w * w3.x;
            float m1 = lo.y + bb.y + eav.x * w0.y + eav.y * w1.y + eav.z * w2.y + eav.w * w3.y;
            float m2 = hi.x + bb.z + eav.x * w0.z + eav.y * w1.z + eav.z * w2.z + eav.w * w3.z;
            float m3 = hi.y + bb.w + eav.x * w0.w + eav.y * w1.w + eav.z * w2.w + eav.w * w3.w;
            m0 = fmaxf(m0, 0.f); m1 = fmaxf(m1, 0.f);
            m2 = fmaxf(m2, 0.f); m3 = fmaxf(m3, 0.f);
            float* dptr = h + (size_t)dst * H + lane * 4;
            asm volatile("red.global.add.v4.f32 [%0], {%1,%2,%3,%4};"
                         :: "l"(dptr), "f"(m0), "f"(m1), "f"(m2), "f"(m3)
                         : "memory");
        }
    }
}

// ---------------------------------------------------------------------------
// Warp-specialized fused 2-layer MLP (bf16x3 mma.sync):
//   convert(t): split across BOTH groups at iteration top (rows 0-63 / 64-127)
//   warps 0-7  (group 0): GEMM1(t) -> silu -> Ts[buf]
//   warps 8-15 (group 1): GEMM2(t-1) -> bias -> stores:
//     non-last (h_out != 0): h_out (fp32) + xh_out (fp16 mirror); no fp32 x
//     last     (h_out == 0): x_out (the harness output) only
// ---------------------------------------------------------------------------
__global__ void __launch_bounds__(MLP_THREADS, 1)
mlp_kernel(const float* __restrict__ h_in,
           const uint32_t* __restrict__ wfrag,
           const float* __restrict__ b1, const float* __restrict__ b2,
           float* __restrict__ x_out, float* __restrict__ h_out,
           uint32_t* __restrict__ xh_out, int n) {
    extern __shared__ __align__(16) uint32_t sm[];
    uint32_t* Hs_hi = sm;
    uint32_t* Hs_lo = sm + TILE_U32;
    // Ts buffers: sm + (2 + 2*buf)*TILE_U32 (hi), +TILE_U32 (lo)

    int tid = threadIdx.x, w = tid >> 5, lane = tid & 31;
    int group = w >> 3;          // 0 = W1 group, 1 = W2/store group
    int wl = w & 7;              // warp slot within group (16-col slice)
    int gt = tid & 255;          // thread index within group
    int gid = lane >> 2, tg = lane & 3;

    // this warp's weight fragments for ITS matrix only (64 regs)
    uint2 wB[2][2][8];           // [hl][nb][ks]
    {
        const uint2* wp = (const uint2*)wfrag + (size_t)wl * 4 * 2 * 8 * 32;
        #pragma unroll
        for (int hl = 0; hl < 2; hl++)
            #pragma unroll
            for (int nb = 0; nb < 2; nb++)
                #pragma unroll
                for (int ks = 0; ks < 8; ks++)
                    wB[hl][nb][ks] =
                        wp[((((group * 2 + hl) * 2) + nb) * 8 + ks) * 32 + lane];
    }
    const float* bsrc = group ? b2 : b1;
    float2 bv[2];
    #pragma unroll
    for (int nb = 0; nb < 2; nb++)
        bv[nb] = *(const float2*)(bsrc + 16 * wl + 8 * nb + 2 * tg);

    int ntiles = (n + TM - 1) / TM;
    int bid = blockIdx.x;
    int ntl = (bid < ntiles) ? ((ntiles - 1 - bid) / gridDim.x + 1) : 0;

    #pragma unroll 1
    for (int it = 0; it <= ntl; it++) {
        int buf = it & 1;

        // ---- convert tile t=it (both groups, half each) ----
        if (it < ntl) {
            int row0 = (bid + it * gridDim.x) * TM;
            #pragma unroll 4
            for (int it2 = 0; it2 < 8; it2++) {
                int i = gt + (group * 8 + it2) * 256;
                int row = i >> 5;
                int c4 = i & 31;
                float4 v = make_float4(0.f, 0.f, 0.f, 0.f);
                if (row0 + row < n)
                    v = *(const float4*)(h_in + (size_t)(row0 + row) * H + c4 * 4);
                __nv_bfloat16 hx = __float2bfloat16(v.x), hy = __float2bfloat16(v.y);
                __nv_bfloat16 hz = __float2bfloat16(v.z), hw = __float2bfloat16(v.w);
                int base = row * ROWSTRIDE;
                int p0 = pidx(2 * c4), p1 = pidx(2 * c4 + 1);
                Hs_hi[base + p0] = pack_bf16(__bfloat162float(hx), __bfloat162float(hy));
                Hs_hi[base + p1] = pack_bf16(__bfloat162float(hz), __bfloat162float(hw));
                Hs_lo[base + p0] = pack_bf16(v.x - __bfloat162float(hx), v.y - __bfloat162float(hy));
                Hs_lo[base + p1] = pack_bf16(v.z - __bfloat162float(hz), v.w - __bfloat162float(hw));
            }
        }
        __syncthreads();

        if (group == 0) {
            if (it < ntl) {
                // ---- GEMM1 + silu -> Ts[buf] ----
                uint32_t* Ts_hi = sm + (2 + 2 * buf) * TILE_U32;
                uint32_t* Ts_lo = Ts_hi + TILE_U32;
                #pragma unroll 1
                for (int mb = 0; mb < 8; mb++) {
                    float acc[2][4] = {{0.f, 0.f, 0.f, 0.f}, {0.f, 0.f, 0.f, 0.f}};
                    int ra = (mb * 16 + gid) * ROWSTRIDE;
                    int rb = ra + 8 * ROWSTRIDE;
                    #pragma unroll
                    for (int ks = 0; ks < 8; ks++) {
                        uint2 ah  = *(const uint2*)(Hs_hi + ra + ks * 8 + tg * 2);
                        uint2 ahb = *(const uint2*)(Hs_hi + rb + ks * 8 + tg * 2);
                        uint2 al  = *(const uint2*)(Hs_lo + ra + ks * 8 + tg * 2);
                        uint2 alb = *(const uint2*)(Hs_lo + rb + ks * 8 + tg * 2);
                        #pragma unroll
                        for (int nb = 0; nb < 2; nb++) {
                            uint2 bh = wB[0][nb][ks];
                            uint2 bl = wB[1][nb][ks];
                            MMA_BF16(acc[nb], ah.x, ahb.x, ah.y, ahb.y, bh.x, bh.y);
                            MMA_BF16(acc[nb], al.x, alb.x, al.y, alb.y, bh.x, bh.y);
                            MMA_BF16(acc[nb], ah.x, ahb.x, ah.y, ahb.y, bl.x, bl.y);
                        }
                    }
                    int sa = (mb * 16 + gid) * ROWSTRIDE + 8 * wl + 2 * tg;
                    int sb = sa + 8 * ROWSTRIDE;
                    #pragma unroll
                    for (int nb = 0; nb < 2; nb++) {
                        float f0 = silu_fast(acc[nb][0] + bv[nb].x);
                        float f1 = silu_fast(acc[nb][1] + bv[nb].y);
                        float f2 = silu_fast(acc[nb][2] + bv[nb].x);
                        float f3 = silu_fast(acc[nb][3] + bv[nb].y);
                        __nv_bfloat16 h0 = __float2bfloat16(f0), h1 = __float2bfloat16(f1);
                        __nv_bfloat16 h2 = __float2bfloat16(f2), h3 = __float2bfloat16(f3);
                        Ts_hi[sa + nb] = pack_bf16(__bfloat162float(h0), __bfloat162float(h1));
                        Ts_hi[sb + nb] = pack_bf16(__bfloat162float(h2), __bfloat162float(h3));
                        Ts_lo[sa + nb] = pack_bf16(f0 - __bfloat162float(h0), f1 - __bfloat162float(h1));
                        Ts_lo[sb + nb] = pack_bf16(f2 - __bfloat162float(h2), f3 - __bfloat162float(h3));
                    }
                }
            }
        } else {
            if (it > 0) {
                int row0 = (bid + (it - 1) * gridDim.x) * TM;
                uint32_t* Ts_hi = sm + (2 + 2 * (buf ^ 1)) * TILE_U32;
                uint32_t* Ts_lo = Ts_hi + TILE_U32;
                #pragma unroll 1
                for (int mb = 0; mb < 8; mb++) {
                    float acc[2][4] = {{0.f, 0.f, 0.f, 0.f}, {0.f, 0.f, 0.f, 0.f}};
                    int ra = (mb * 16 + gid) * ROWSTRIDE;
                    int rb = ra + 8 * ROWSTRIDE;
                    #pragma unroll
                    for (int ks = 0; ks < 8; ks++) {
                        uint2 ah  = *(const uint2*)(Ts_hi + ra + ks * 8 + tg * 2);
                        uint2 ahb = *(const uint2*)(Ts_hi + rb + ks * 8 + tg * 2);
                        uint2 al  = *(const uint2*)(Ts_lo + ra + ks * 8 + tg * 2);
                        uint2 alb = *(const uint2*)(Ts_lo + rb + ks * 8 + tg * 2);
                        #pragma unroll
                        for (int nb = 0; nb < 2; nb++) {
                            uint2 bh = wB[0][nb][ks];
                            uint2 bl = wB[1][nb][ks];
                            MMA_BF16(acc[nb], ah.x, ahb.x, ah.y, ahb.y, bh.x, bh.y);
                            MMA_BF16(acc[nb], al.x, alb.x, al.y, alb.y, bh.x, bh.y);
                            MMA_BF16(acc[nb], ah.x, ahb.x, ah.y, ahb.y, bl.x, bl.y);
                        }
                    }
                    int r0 = row0 + mb * 16 + gid;
                    int r1 = r0 + 8;
                    #pragma unroll
                    for (int nb = 0; nb < 2; nb++) {
                        int col = 16 * wl + 8 * nb + 2 * tg;
                        if (r0 < n) {
                            float2 o0 = make_float2(acc[nb][0] + bv[nb].x,
                                                    acc[nb][1] + bv[nb].y);
                            if (h_out) {
                                *(float2*)(h_out + (size_t)r0 * H + col) = o0;
                                xh_out[(size_t)r0 * 64 + (col >> 1)] = pack_f16(o0.x, o0.y);
                            } else {
                                *(float2*)(x_out + (size_t)r0 * H + col) = o0;
                            }
                        }
                        if (r1 < n) {
                            float2 o1 = make_float2(acc[nb][2] + bv[nb].x,
                                                    acc[nb][3] + bv[nb].y);
                            if (h_out) {
                                *(float2*)(h_out + (size_t)r1 * H + col) = o1;
                                xh_out[(size_t)r1 * 64 + (col >> 1)] = pack_f16(o1.x, o1.y);
                            } else {
                                *(float2*)(x_out + (size_t)r1 * H + col) = o1;
                            }
                        }
                    }
                }
            }
        }
        __syncthreads();
    }
}

extern "C" void kernel_launch(void* const* d_in, const int* in_sizes, int n_in,
                              void* d_out, int out_size) {
    const float* emb       = (const float*)d_in[0];
    const float* We        = (const float*)d_in[1];
    const float* be        = (const float*)d_in[2];
    const float* W1        = (const float*)d_in[3];
    const float* b1        = (const float*)d_in[4];
    const float* W2        = (const float*)d_in[5];
    const float* b2        = (const float*)d_in[6];
    const float* edge_attr = (const float*)d_in[7];
    const int*   z         = (const int*)d_in[8];
    const int*   ei        = (const int*)d_in[9];
    const int*   bv        = (const int*)d_in[10];

    int n = in_sizes[8];
    int E = in_sizes[9] / 2;
    float* out = (float*)d_out;

    float *gh;
    uint32_t *gwf, *gxh;
    cudaGetSymbolAddress((void**)&gh, g_h);
    cudaGetSymbolAddress((void**)&gwf, g_wfrag);
    cudaGetSymbolAddress((void**)&gxh, g_xh);

    cudaFuncSetAttribute(mlp_kernel, cudaFuncAttributeMaxDynamicSharedMemorySize,
                         MLP_SMEM);

    int nembed = (n * 32 + 255) / 256;
    int nwprep = (WPREP_TOTAL + 255) / 256;
    int nbatch = (n + 255) / 256;
    float* out_tail = (out_size >= n * H + n) ? (out + (size_t)n * H) : nullptr;
    prep_kernel<<<nembed + nwprep + nbatch, 256>>>(emb, z, gh, gxh, n, nembed,
                                                   nwprep, W1, W2, bv, out_tail);

    for (int l = 0; l < 3; l++) {
        edge_kernel<<<4096, 256>>>(gxh, gh, edge_attr, ei,
                                   We + (size_t)l * 4 * H, be + (size_t)l * H, E);
        bool last = (l == 2);
        mlp_kernel<<<148, MLP_THREADS, MLP_SMEM>>>(
            gh,
            gwf + (size_t)l * 8 * 4 * 2 * 8 * 32 * 2,
            b1 + (size_t)l * H, b2 + (size_t)l * H,
            last ? out : nullptr,
            last ? nullptr : gh,
            gxh,
            n);
    }
}